// round 3
// baseline (speedup 1.0000x reference)
#include <cuda_runtime.h>
#include <cuda_bf16.h>

// Per-batch pixel-space affine coefficients:
// g_tf[b*3 + i] = {A_d, A_h, A_w, O} such that
//   pixel_coord_i(d,h,w) = A_d*d + A_h*h + A_w*w + O
__device__ float4 g_tf[24];

// ---------------------------------------------------------------------------
// Tiny pre-kernel: analytic least-squares (AtA = 8I exactly) -> 12 coeffs/batch
// ---------------------------------------------------------------------------
__global__ void tf_kernel(const float* __restrict__ u) {
    int b = threadIdx.x;
    if (b >= 8) return;

    float X0[3] = {0.f, 0.f, 0.f};  // X[0][i]  (slope wrt mesh_z / d)
    float X1[3] = {0.f, 0.f, 0.f};  // X[1][i]  (slope wrt mesh_y / h)
    float X2[3] = {0.f, 0.f, 0.f};  // X[2][i]  (slope wrt mesh_x / w)
    float X3[3] = {0.f, 0.f, 0.f};  // X[3][i]  (constant)

#pragma unroll
    for (int n = 0; n < 8; n++) {
        float c0 = ((n >> 2) & 1) ? 1.f : -1.f;
        float c1 = ((n >> 1) & 1) ? 1.f : -1.f;
        float c2 = ( n       & 1) ? 1.f : -1.f;
        float cc[3] = {c0, c1, c2};
#pragma unroll
        for (int i = 0; i < 3; i++) {
            // random_scale = (1 - SCALE) + SCALE*u,  SCALE = 0.2
            float s  = fmaf(0.2f, u[b * 24 + n * 3 + i], 0.8f);
            float cs = cc[i] * s;   // src corner coordinate (dim i)
            X0[i] += c0 * cs;
            X1[i] += c1 * cs;
            X2[i] += c2 * cs;
            X3[i] += cs;
        }
    }

    const float kk = 63.5f * (2.0f / 127.0f);  // linspace step folded with (s-1)/2
#pragma unroll
    for (int i = 0; i < 3; i++) {
        float x0 = X0[i] * 0.125f;
        float x1 = X1[i] * 0.125f;
        float x2 = X2[i] * 0.125f;
        float x3 = X3[i] * 0.125f;
        float4 t;
        t.x = kk * x0;                                    // slope wrt d
        t.y = kk * x1;                                    // slope wrt h
        t.z = kk * x2;                                    // slope wrt w
        t.w = 63.5f * (x3 + 1.0f - x0 - x1 - x2);         // offset at (0,0,0)
        g_tf[b * 3 + i] = t;
    }
}

// ---------------------------------------------------------------------------
// Main resample kernel: 1 thread per output voxel, trilinear, zero boundary
// ---------------------------------------------------------------------------
__global__ void __launch_bounds__(256)
warp_kernel(const float* __restrict__ img, float* __restrict__ out) {
    unsigned idx = blockIdx.x * 256u + threadIdx.x;      // [0, 8*128^3)
    int w = idx & 127;
    int h = (idx >> 7) & 127;
    int d = (idx >> 14) & 127;
    int b = idx >> 21;

    const float4* tf = g_tf + b * 3;
    float4 Tz = __ldg(tf + 0);
    float4 Ty = __ldg(tf + 1);
    float4 Tx = __ldg(tf + 2);

    float fd = (float)d, fh = (float)h, fw = (float)w;
    float pz = fmaf(Tz.x, fd, fmaf(Tz.y, fh, fmaf(Tz.z, fw, Tz.w)));
    float py = fmaf(Ty.x, fd, fmaf(Ty.y, fh, fmaf(Ty.z, fw, Ty.w)));
    float px = fmaf(Tx.x, fd, fmaf(Tx.y, fh, fmaf(Tx.z, fw, Tx.w)));

    float gz = floorf(pz), gy = floorf(py), gx = floorf(px);
    float rz = pz - gz, ry = py - gy, rx = px - gx;
    int z0 = (int)gz, y0 = (int)gy, x0 = (int)gx;
    int z1 = z0 + 1, y1 = y0 + 1, x1 = x0 + 1;

    // zero-boundary: fold validity into the per-dim weights
    float az0 = ((unsigned)z0 < 128u) ? (1.f - rz) : 0.f;
    float az1 = ((unsigned)z1 < 128u) ? rz          : 0.f;
    float ay0 = ((unsigned)y0 < 128u) ? (1.f - ry) : 0.f;
    float ay1 = ((unsigned)y1 < 128u) ? ry          : 0.f;
    float ax0 = ((unsigned)x0 < 128u) ? (1.f - rx) : 0.f;
    float ax1 = ((unsigned)x1 < 128u) ? rx          : 0.f;

    // clamped indices (loads are always in-bounds; zero weight kills invalid)
    int zc0 = min(max(z0, 0), 127), zc1 = min(max(z1, 0), 127);
    int yc0 = min(max(y0, 0), 127), yc1 = min(max(y1, 0), 127);
    int xc0 = min(max(x0, 0), 127), xc1 = min(max(x1, 0), 127);

    const float* base = img + ((size_t)b << 21);
    const float* r00 = base + (zc0 << 14) + (yc0 << 7);
    const float* r01 = base + (zc0 << 14) + (yc1 << 7);
    const float* r10 = base + (zc1 << 14) + (yc0 << 7);
    const float* r11 = base + (zc1 << 14) + (yc1 << 7);

    float v00 = fmaf(ax0, __ldg(r00 + xc0), ax1 * __ldg(r00 + xc1));
    float v01 = fmaf(ax0, __ldg(r01 + xc0), ax1 * __ldg(r01 + xc1));
    float v10 = fmaf(ax0, __ldg(r10 + xc0), ax1 * __ldg(r10 + xc1));
    float v11 = fmaf(ax0, __ldg(r11 + xc0), ax1 * __ldg(r11 + xc1));

    float v0 = fmaf(ay0, v00, ay1 * v01);
    float v1 = fmaf(ay0, v10, ay1 * v11);
    out[idx] = fmaf(az0, v0, az1 * v1);
}

extern "C" void kernel_launch(void* const* d_in, const int* in_sizes, int n_in,
                              void* d_out, int out_size) {
    const float* img = (const float*)d_in[0];   // [8,128,128,128,1] fp32
    const float* u   = (const float*)d_in[1];   // [8,8,3] fp32
    float* out = (float*)d_out;

    tf_kernel<<<1, 8>>>(u);
    // 8 * 128^3 = 16,777,216 voxels / 256 threads = 65,536 blocks
    warp_kernel<<<65536, 256>>>(img, out);
}

// round 16
// speedup vs baseline: 1.7073x; 1.7073x over previous
#include <cuda_runtime.h>
#include <cuda_bf16.h>

// Per-batch pixel-space affine coefficients:
// g_tf[b*3 + i] = {A_d, A_h, A_w, O} such that
//   pixel_coord_i(d,h,w) = A_d*d + A_h*h + A_w*w + O
__device__ float4 g_tf[24];

// ---------------------------------------------------------------------------
// Tiny pre-kernel: analytic least-squares (AtA = 8I exactly) -> 12 coeffs/batch
// ---------------------------------------------------------------------------
__global__ void tf_kernel(const float* __restrict__ u) {
    int b = threadIdx.x;
    if (b >= 8) return;

    float X0[3] = {0.f, 0.f, 0.f};
    float X1[3] = {0.f, 0.f, 0.f};
    float X2[3] = {0.f, 0.f, 0.f};
    float X3[3] = {0.f, 0.f, 0.f};

#pragma unroll
    for (int n = 0; n < 8; n++) {
        float c0 = ((n >> 2) & 1) ? 1.f : -1.f;
        float c1 = ((n >> 1) & 1) ? 1.f : -1.f;
        float c2 = ( n       & 1) ? 1.f : -1.f;
        float cc[3] = {c0, c1, c2};
#pragma unroll
        for (int i = 0; i < 3; i++) {
            float s  = fmaf(0.2f, u[b * 24 + n * 3 + i], 0.8f);
            float cs = cc[i] * s;
            X0[i] += c0 * cs;
            X1[i] += c1 * cs;
            X2[i] += c2 * cs;
            X3[i] += cs;
        }
    }

    const float kk = 63.5f * (2.0f / 127.0f);
#pragma unroll
    for (int i = 0; i < 3; i++) {
        float x0 = X0[i] * 0.125f;
        float x1 = X1[i] * 0.125f;
        float x2 = X2[i] * 0.125f;
        float x3 = X3[i] * 0.125f;
        float4 t;
        t.x = kk * x0;                                    // slope wrt d
        t.y = kk * x1;                                    // slope wrt h
        t.z = kk * x2;                                    // slope wrt w
        t.w = 63.5f * (x3 + 1.0f - x0 - x1 - x2);         // offset at (0,0,0)
        g_tf[b * 3 + i] = t;
    }
}

// ---------------------------------------------------------------------------
// Resample kernel: 4 voxels/thread stacked along h (lanes stay consecutive
// in w -> baseline gather coalescing), interior fast path, trilinear.
// ---------------------------------------------------------------------------
__global__ void __launch_bounds__(256)
warp_kernel(const float* __restrict__ img, float* __restrict__ out) {
    unsigned t = blockIdx.x * 256u + threadIdx.x;     // [0, 8*128*32*128)
    int w  = t & 127;
    int h  = ((t >> 7) & 31) << 2;                    // h in {0,4,...,124}
    int d  = (t >> 12) & 127;
    int b  = t >> 19;
    unsigned idx = ((unsigned)b << 21) | ((unsigned)d << 14)
                 | ((unsigned)h << 7)  | (unsigned)w;

    const float4* tf = g_tf + b * 3;
    float4 Tz = __ldg(tf + 0);
    float4 Ty = __ldg(tf + 1);
    float4 Tx = __ldg(tf + 2);

    float fd = (float)d, fh = (float)h, fw = (float)w;
    float pz = fmaf(Tz.x, fd, fmaf(Tz.y, fh, fmaf(Tz.z, fw, Tz.w)));
    float py = fmaf(Ty.x, fd, fmaf(Ty.y, fh, fmaf(Ty.z, fw, Ty.w)));
    float px = fmaf(Tx.x, fd, fmaf(Tx.y, fh, fmaf(Tx.z, fw, Tx.w)));

    float PX[4], PY[4], PZ[4];
#pragma unroll
    for (int v = 0; v < 4; v++) {
        PX[v] = px; PY[v] = py; PZ[v] = pz;
        px += Tx.y; py += Ty.y; pz += Tz.y;   // advance one step in h
    }

    int   IX[4], IY[4], IZ[4];
    float FX[4], FY[4], FZ[4];
    unsigned fast = 1u;
#pragma unroll
    for (int v = 0; v < 4; v++) {
        IX[v] = __float2int_rd(PX[v]); FX[v] = PX[v] - (float)IX[v];
        IY[v] = __float2int_rd(PY[v]); FY[v] = PY[v] - (float)IY[v];
        IZ[v] = __float2int_rd(PZ[v]); FZ[v] = PZ[v] - (float)IZ[v];
        fast &= ((unsigned)IX[v] <= 126u) & ((unsigned)IY[v] <= 126u)
              & ((unsigned)IZ[v] <= 126u);
    }

    const float* base = img + ((size_t)b << 21);
    float res[4];

    if (fast) {
        // whole 2x2x2 footprint strictly in-bounds for all 4 voxels
#pragma unroll
        for (int v = 0; v < 4; v++) {
            const float* p = base + (IZ[v] << 14) + (IY[v] << 7) + IX[v];
            float v000 = __ldg(p);             float v001 = __ldg(p + 1);
            float v010 = __ldg(p + 128);       float v011 = __ldg(p + 129);
            float v100 = __ldg(p + 16384);     float v101 = __ldg(p + 16385);
            float v110 = __ldg(p + 16512);     float v111 = __ldg(p + 16513);

            float wx1 = FX[v], wx0 = 1.f - wx1;
            float wy1 = FY[v], wy0 = 1.f - wy1;
            float wz1 = FZ[v], wz0 = 1.f - wz1;

            float a  = fmaf(wx0, v000, wx1 * v001);
            float c  = fmaf(wx0, v010, wx1 * v011);
            float e  = fmaf(wx0, v100, wx1 * v101);
            float g  = fmaf(wx0, v110, wx1 * v111);
            float f0 = fmaf(wy0, a, wy1 * c);
            float f1 = fmaf(wy0, e, wy1 * g);
            res[v]   = fmaf(wz0, f0, wz1 * f1);
        }
    } else {
        // boundary path: clamped indices, validity folded into weights
#pragma unroll
        for (int v = 0; v < 4; v++) {
            int z0 = IZ[v], y0 = IY[v], x0 = IX[v];
            int z1 = z0 + 1, y1 = y0 + 1, x1 = x0 + 1;
            float rz = FZ[v], ry = FY[v], rx = FX[v];

            float az0 = ((unsigned)z0 < 128u) ? (1.f - rz) : 0.f;
            float az1 = ((unsigned)z1 < 128u) ? rz          : 0.f;
            float ay0 = ((unsigned)y0 < 128u) ? (1.f - ry) : 0.f;
            float ay1 = ((unsigned)y1 < 128u) ? ry          : 0.f;
            float ax0 = ((unsigned)x0 < 128u) ? (1.f - rx) : 0.f;
            float ax1 = ((unsigned)x1 < 128u) ? rx          : 0.f;

            int zc0 = min(max(z0, 0), 127), zc1 = min(max(z1, 0), 127);
            int yc0 = min(max(y0, 0), 127), yc1 = min(max(y1, 0), 127);
            int xc0 = min(max(x0, 0), 127), xc1 = min(max(x1, 0), 127);

            const float* r00 = base + (zc0 << 14) + (yc0 << 7);
            const float* r01 = base + (zc0 << 14) + (yc1 << 7);
            const float* r10 = base + (zc1 << 14) + (yc0 << 7);
            const float* r11 = base + (zc1 << 14) + (yc1 << 7);

            float v00 = fmaf(ax0, __ldg(r00 + xc0), ax1 * __ldg(r00 + xc1));
            float v01 = fmaf(ax0, __ldg(r01 + xc0), ax1 * __ldg(r01 + xc1));
            float v10 = fmaf(ax0, __ldg(r10 + xc0), ax1 * __ldg(r10 + xc1));
            float v11 = fmaf(ax0, __ldg(r11 + xc0), ax1 * __ldg(r11 + xc1));

            float v0 = fmaf(ay0, v00, ay1 * v01);
            float v1 = fmaf(ay0, v10, ay1 * v11);
            res[v]   = fmaf(az0, v0, az1 * v1);
        }
    }

    // 4 coalesced STG.32 (lanes consecutive in w); h-stride = 128 floats
#pragma unroll
    for (int v = 0; v < 4; v++)
        out[idx + (unsigned)(v << 7)] = res[v];
}

extern "C" void kernel_launch(void* const* d_in, const int* in_sizes, int n_in,
                              void* d_out, int out_size) {
    const float* img = (const float*)d_in[0];   // [8,128,128,128,1] fp32
    const float* u   = (const float*)d_in[1];   // [8,8,3] fp32
    float* out = (float*)d_out;

    tf_kernel<<<1, 8>>>(u);
    // 8*128^3 / 4 voxels-per-thread = 4,194,304 threads / 256 = 16384 blocks
    warp_kernel<<<16384, 256>>>(img, out);
}